// round 15
// baseline (speedup 1.0000x reference)
#include <cuda_runtime.h>
#include <cuda_fp16.h>
#include <math.h>

// ---------------- problem constants ----------------
#define MN   50000
#define EDG  800000
#define NB   8
#define FEATD 128
#define HIDD  64
#define DIMD  32
#define CAP  64          // per-row edge bucket capacity (P(overflow) ~ e^-40)
#define MINN 1e-15f
#define CLIPV (1.0f - 1e-7f)
#define MAXNV (1.0f - 4e-3f)
#define FULLM 0xffffffffu

// ---------------- static scratch (no allocs allowed) ----------------
__device__ float g_xhyp[MN * FEATD];              // proj(expmap0(x))
__device__ float g_xn1[MN];                       // ||x_hyp|| per node
__device__ __align__(256) __half g_bufh[(size_t)NB * MN * HIDD]; // xt in fp16
__device__ float g_h[(size_t)NB * MN * HIDD];     // layer outputs (ball points)
__device__ float g_xn2[NB * MN];                  // ||h1|| per (branch,node)
__device__ int   g_count[NB * MN];                // zeroed by previous call's k_combine
__device__ int2  g_epack[(size_t)NB * MN * CAP];  // packed (col, val) per row bucket
__device__ float g_hb1[NB * HIDD];
__device__ float g_hb1n2[NB];
__device__ float g_hb2[NB * DIMD];
__device__ float g_hb2n2[NB];

__device__ __forceinline__ float wsum(float v) {
#pragma unroll
    for (int o = 16; o; o >>= 1) v += __shfl_xor_sync(FULLM, v, o);
    return v;
}
__device__ __forceinline__ float hsum8(float v) {
#pragma unroll
    for (int o = 4; o; o >>= 1) v += __shfl_xor_sync(FULLM, v, o);
    return v;
}

// packed fp32x2 helpers (Blackwell FFMA2 path)
__device__ __forceinline__ void ffma2(unsigned long long& d, unsigned long long a,
                                      unsigned long long b) {
    asm("fma.rn.f32x2 %0, %1, %2, %0;" : "+l"(d) : "l"(a), "l"(b));
}
__device__ __forceinline__ unsigned long long dup2(float x) {
    unsigned long long r;
    asm("mov.b64 %0, {%1, %1};" : "=l"(r) : "f"(x));
    return r;
}
__device__ __forceinline__ float2 unpk(unsigned long long v) {
    float2 r;
    asm("mov.b64 {%0, %1}, %2;" : "=f"(r.x), "=f"(r.y) : "l"(v));
    return r;
}

// ---------------- direct bucket CSR build (single pass) ----------------
__global__ void k_place(const int* __restrict__ rows, const int* __restrict__ cols,
                        const float* __restrict__ vals) {
    int b = blockIdx.y;
    int e = blockIdx.x * blockDim.x + threadIdx.x;
    size_t be = (size_t)b * EDG + e;
    int r = rows[be];
    int p = atomicAdd(&g_count[b * MN + r], 1);
    if (p < CAP)
        g_epack[((size_t)b * MN + r) * CAP + p] =
            make_int2(cols[be], __float_as_int(vals[be]));
}

// ---------------- x -> ball, fused with bias -> ball ----------------
__global__ void k_xhyp_bias(const float* __restrict__ x,
                            const float* __restrict__ b1,
                            const float* __restrict__ b2) {
    int lane = threadIdx.x & 31;
    if (blockIdx.x < 3125) {
        int m = blockIdx.x * 16 + (threadIdx.x >> 5);
        float u[4];
        float n2 = 0.f;
#pragma unroll
        for (int j = 0; j < 4; j++) {
            u[j] = x[(size_t)m * FEATD + lane + 32 * j];
            n2 += u[j] * u[j];
        }
        n2 = wsum(n2);
        float n = fmaxf(sqrtf(n2), MINN);
        float on = tanhf(n);
        float s = on / n;
        if (on > MAXNV) { s *= MAXNV / on; on = MAXNV; }
#pragma unroll
        for (int j = 0; j < 4; j++) g_xhyp[(size_t)m * FEATD + lane + 32 * j] = s * u[j];
        if (lane == 0) g_xn1[m] = fmaxf(on, MINN);
    } else {
        int wid = threadIdx.x >> 5;
        if (wid < NB) {
            int b = wid;
            float v0 = b1[b * HIDD + lane], v1 = b1[b * HIDD + lane + 32];
            float n = fmaxf(sqrtf(wsum(v0 * v0 + v1 * v1)), MINN);
            float on = tanhf(n);
            float s = on / n;
            if (on > MAXNV) { s *= MAXNV / on; on = MAXNV; }
            g_hb1[b * HIDD + lane] = s * v0;
            g_hb1[b * HIDD + lane + 32] = s * v1;
            if (lane == 0) g_hb1n2[b] = on * on;
        } else {
            int b = wid - 8;
            float v = b2[b * DIMD + lane];
            float n = fmaxf(sqrtf(wsum(v * v)), MINN);
            float on = tanhf(n);
            float s = on / n;
            if (on > MAXNV) { s *= MAXNV / on; on = MAXNV; }
            g_hb2[b * DIMD + lane] = s * v;
            if (lane == 0) g_hb2n2[b] = on * on;
        }
    }
}

// ---------------- SGEMM (f32x2 packed, KC=32) + fused mobius epilogue ----------------
// Tile: 256 rows x N cols, 256 threads, thread tile 8 x CN, K chunked by 32.
// 2 CTAs/SM (reg cap 128); smem traffic = 1 B/MAC. Epilogue -> fp16 g_bufh.
template <int N, int K, bool L1>
__global__ void __launch_bounds__(256, 2) k_gemm(const float* __restrict__ W) {
    constexpr int TM = 256, KC = 32, PX = TM + 4, PW = N + 4;
    constexpr int CN = (N == 64) ? 8 : 4;   // cols per thread (8 tx threads)
    constexpr int CP = CN / 2;              // packed col pairs
    extern __shared__ float smf[];
    float* Xs = smf;             // [KC][PX]
    float* Ws = smf + KC * PX;   // [KC][PW]
    int tid = threadIdx.x, b = blockIdx.y, m0 = blockIdx.x * TM;
    int tx = tid & 7, ty = tid >> 3;   // tx: 8 col-groups, ty: 32 row-groups
    const float* Xb = L1 ? g_xhyp : (g_h + (size_t)b * MN * K);

    unsigned long long acc[8][CP];
#pragma unroll
    for (int i = 0; i < 8; i++)
#pragma unroll
        for (int p = 0; p < CP; p++) acc[i][p] = 0ull;

    for (int kc0 = 0; kc0 < K; kc0 += KC) {
        __syncthreads();
        // fill X: TM rows x KC cols; t -> (m = t>>3, k4 = t&7)
#pragma unroll
        for (int it = 0; it < TM * (KC / 4) / 256; it++) {
            int t = tid + it * 256;
            int m = t >> 3, k4 = t & 7;
            int gm = m0 + m;
            float4 v = make_float4(0.f, 0.f, 0.f, 0.f);
            if (gm < MN) v = *(const float4*)(Xb + (size_t)gm * K + kc0 + k4 * 4);
            Xs[(k4 * 4 + 0) * PX + m] = v.x;
            Xs[(k4 * 4 + 1) * PX + m] = v.y;
            Xs[(k4 * 4 + 2) * PX + m] = v.z;
            Xs[(k4 * 4 + 3) * PX + m] = v.w;
        }
        // fill W: N rows x KC cols
        for (int t = tid; t < N * (KC / 4); t += 256) {
            int n = t >> 3, k4 = t & 7;
            float4 v = *(const float4*)(W + ((size_t)b * N + n) * K + kc0 + k4 * 4);
            Ws[(k4 * 4 + 0) * PW + n] = v.x;
            Ws[(k4 * 4 + 1) * PW + n] = v.y;
            Ws[(k4 * 4 + 2) * PW + n] = v.z;
            Ws[(k4 * 4 + 3) * PW + n] = v.w;
        }
        __syncthreads();
#pragma unroll 8
        for (int k = 0; k < KC; k++) {
            float4 a0 = *(const float4*)(Xs + k * PX + ty * 8);
            float4 a1 = *(const float4*)(Xs + k * PX + ty * 8 + 4);
            float av[8] = {a0.x, a0.y, a0.z, a0.w, a1.x, a1.y, a1.z, a1.w};
            unsigned long long bp[CP];
            const unsigned long long* bq =
                (const unsigned long long*)(Ws + k * PW + tx * CN);
#pragma unroll
            for (int p = 0; p < CP; p++) bp[p] = bq[p];
            unsigned long long ad[8];
#pragma unroll
            for (int i = 0; i < 8; i++) ad[i] = dup2(av[i]);
#pragma unroll
            for (int i = 0; i < 8; i++)
#pragma unroll
                for (int p = 0; p < CP; p++) ffma2(acc[i][p], ad[i], bp[p]);
        }
    }

    // ---- fused epilogue: row owned by 8 lanes (same ty) ----
    float hb[CN];
#pragma unroll
    for (int j = 0; j < CN; j++)
        hb[j] = L1 ? g_hb1[b * N + tx * CN + j] : g_hb2[b * N + tx * CN + j];
    float y2 = L1 ? g_hb1n2[b] : g_hb2n2[b];
#pragma unroll
    for (int i = 0; i < 8; i++) {
        int row = m0 + ty * 8 + i;
        float ac[CN];
#pragma unroll
        for (int p = 0; p < CP; p++) {
            float2 u = unpk(acc[i][p]);
            ac[2 * p] = u.x;
            ac[2 * p + 1] = u.y;
        }
        float s2 = 0.f;
#pragma unroll
        for (int j = 0; j < CN; j++) s2 += ac[j] * ac[j];
        float mxn = fmaxf(sqrtf(hsum8(s2)), MINN);
        float xn = 0.5f;
        if (row < MN) xn = L1 ? g_xn1[row] : g_xn2[(size_t)b * MN + row];
        float arg = mxn / xn * atanhf(fminf(xn, CLIPV));
        float th = tanhf(arg);
        float sc = th / mxn;
        float hn = th;
        if (hn > MAXNV) { sc *= MAXNV / hn; hn = MAXNV; }
        float h[CN];
#pragma unroll
        for (int j = 0; j < CN; j++) h[j] = sc * ac[j];
        float x2 = hn * hn;
        float xyp = 0.f;
#pragma unroll
        for (int j = 0; j < CN; j++) xyp += h[j] * hb[j];
        float xy = hsum8(xyp);
        float den = fmaxf(1.f + 2.f * xy + x2 * y2, MINN);
        float A = (1.f + 2.f * xy + y2) / den;
        float B = (1.f - x2) / den;
#pragma unroll
        for (int j = 0; j < CN; j++) h[j] = A * h[j] + B * hb[j];
        float rp = 0.f;
#pragma unroll
        for (int j = 0; j < CN; j++) rp += h[j] * h[j];
        float rn = fmaxf(sqrtf(hsum8(rp)), MINN);
        float pf = 1.f;
        if (rn > MAXNV) { pf = MAXNV / rn; rn = MAXNV; }
        float t = atanhf(fminf(rn, CLIPV)) / rn * pf;
        if (row < MN) {
            __half2 hv[CP];
#pragma unroll
            for (int p = 0; p < CP; p++)
                hv[p] = __float22half2_rn(make_float2(t * h[2 * p], t * h[2 * p + 1]));
            __half* o = g_bufh + ((size_t)b * MN + row) * N + tx * CN;
            if (CP == 4) *(uint4*)o = *(uint4*)hv;
            else         *(uint2*)o = *(uint2*)hv;
        }
    }
}

// ---------------- bucket gather agg (fp16 xt, 16-wide MLP) + fused nonlinearity ----------------
template <int D>
__global__ void k_agg() {
    int b = blockIdx.y;
    int m = blockIdx.x * 8 + (threadIdx.x >> 5);
    if (m >= MN) return;
    int lane = threadIdx.x & 31;
    int cnt = min(g_count[b * MN + m], CAP);
    const int2* __restrict__ ep = g_epack + ((size_t)b * MN + m) * CAP;
    const __half* __restrict__ xt = g_bufh + (size_t)b * MN * D;
    float a0 = 0.f, a1 = 0.f, b0 = 0.f, b1 = 0.f;
    float p0 = 0.f, p1 = 0.f, q0 = 0.f, q1 = 0.f;
    for (int base = 0; base < cnt; base += 32) {
        int nb2 = min(32, cnt - base);
        int c = 0; float v = 0.f;
        if (lane < nb2) {
            int2 pk = ep[base + lane];
            c = pk.x;
            v = __int_as_float(pk.y);
        }
        int j = 0;
        // 16-wide batch: issue all 16 gathers before consuming (MLP=16/lane)
        for (; j + 16 <= nb2; j += 16) {
            int   e[16];
            float w[16];
#pragma unroll
            for (int u = 0; u < 16; u++) {
                e[u] = __shfl_sync(FULLM, c, j + u);
                w[u] = __shfl_sync(FULLM, v, j + u);
            }
            if (D == 64) {
                float2 r[16];
#pragma unroll
                for (int u = 0; u < 16; u++)
                    r[u] = __half22float2(__ldg((const __half2*)(xt + (size_t)e[u] * 64) + lane));
#pragma unroll
                for (int u = 0; u < 16; u += 4) {
                    a0 += w[u] * r[u].x;     a1 += w[u] * r[u].y;
                    b0 += w[u+1] * r[u+1].x; b1 += w[u+1] * r[u+1].y;
                    p0 += w[u+2] * r[u+2].x; p1 += w[u+2] * r[u+2].y;
                    q0 += w[u+3] * r[u+3].x; q1 += w[u+3] * r[u+3].y;
                }
            } else {
                float r[16];
#pragma unroll
                for (int u = 0; u < 16; u++)
                    r[u] = __half2float(__ldg(xt + (size_t)e[u] * 32 + lane));
#pragma unroll
                for (int u = 0; u < 16; u += 4) {
                    a0 += w[u] * r[u];     b0 += w[u+1] * r[u+1];
                    p0 += w[u+2] * r[u+2]; q0 += w[u+3] * r[u+3];
                }
            }
        }
        // 4-wide
        for (; j + 4 <= nb2; j += 4) {
            int   e[4];
            float w[4];
#pragma unroll
            for (int u = 0; u < 4; u++) {
                e[u] = __shfl_sync(FULLM, c, j + u);
                w[u] = __shfl_sync(FULLM, v, j + u);
            }
            if (D == 64) {
                float2 r[4];
#pragma unroll
                for (int u = 0; u < 4; u++)
                    r[u] = __half22float2(__ldg((const __half2*)(xt + (size_t)e[u] * 64) + lane));
                a0 += w[0] * r[0].x; a1 += w[0] * r[0].y;
                b0 += w[1] * r[1].x; b1 += w[1] * r[1].y;
                p0 += w[2] * r[2].x; p1 += w[2] * r[2].y;
                q0 += w[3] * r[3].x; q1 += w[3] * r[3].y;
            } else {
                float r[4];
#pragma unroll
                for (int u = 0; u < 4; u++)
                    r[u] = __half2float(__ldg(xt + (size_t)e[u] * 32 + lane));
                a0 += w[0] * r[0]; b0 += w[1] * r[1];
                p0 += w[2] * r[2]; q0 += w[3] * r[3];
            }
        }
        for (; j < nb2; j++) {
            int ej = __shfl_sync(FULLM, c, j);
            float wj = __shfl_sync(FULLM, v, j);
            if (D == 64) {
                float2 r = __half22float2(__ldg((const __half2*)(xt + (size_t)ej * 64) + lane));
                a0 += wj * r.x; a1 += wj * r.y;
            } else {
                a0 += wj * __half2float(__ldg(xt + (size_t)ej * 32 + lane));
            }
        }
    }
    a0 += b0 + p0 + q0;
    a1 += b1 + p1 + q1;
    // h = proj(expmap0(agg))
    float n = fmaxf(sqrtf(wsum(a0 * a0 + a1 * a1)), MINN);
    float th = tanhf(n);
    float s = th / n;
    float h0 = s * a0, h1 = s * a1;
    float hn = th;
    if (hn > MAXNV) { float f = MAXNV / hn; h0 *= f; h1 *= f; hn = MAXNV; }
    // u = relu(logmap0(h))
    float lt = atanhf(fminf(hn, CLIPV)) / fmaxf(hn, MINN);
    float u0 = fmaxf(lt * h0, 0.f);
    float u1 = fmaxf(lt * h1, 0.f);
    // o = proj(expmap0(u))
    float un = fmaxf(sqrtf(wsum(u0 * u0 + u1 * u1)), MINN);
    float ot = tanhf(un);
    float os = ot / un;
    float o0 = os * u0, o1 = os * u1;
    float on = ot;
    if (on > MAXNV) { float f = MAXNV / on; o0 *= f; o1 *= f; on = MAXNV; }
    float* out = g_h + ((size_t)b * MN + m) * D;
    if (D == 64) {
        ((float2*)out)[lane] = make_float2(o0, o1);
        if (lane == 0) g_xn2[b * MN + m] = fmaxf(on, MINN);
    } else {
        out[lane] = o0;
    }
}

// ---------------- final fold + attention-agg row0 (+ reset g_count) ----------------
__global__ void k_combine(float* __restrict__ out) {
    // reset edge counters for the next invocation (deterministic per-call state)
    int gid = blockIdx.x * blockDim.x + threadIdx.x;
    if (gid < NB * MN) g_count[gid] = 0;

    int m = blockIdx.x * 8 + (threadIdx.x >> 5);
    if (m >= MN) return;
    int lane = threadIdx.x & 31;
    float h[NB], nb[NB], sw[NB], wn2[NB];
#pragma unroll
    for (int b = 0; b < NB; b++) {
        h[b] = g_h[((size_t)b * MN + m) * DIMD + lane];
        nb[b] = fmaxf(sqrtf(wsum(h[b] * h[b])), MINN);
        float a = tanhf(0.125f * atanhf(fminf(nb[b], CLIPV)));
        sw[b] = a / nb[b];
        wn2[b] = a * a;
    }
    float t = sw[0] * h[0];
#pragma unroll
    for (int b = 1; b < NB; b++) {
        float x2 = wsum(t * t);
        float wv = sw[b] * h[b];
        float y2 = wn2[b];
        float xy = wsum(t * wv);
        float den = fmaxf(1.f + 2.f * xy + x2 * y2, MINN);
        t = ((1.f + 2.f * xy + y2) * t + (1.f - x2) * wv) / den;
    }
    float acc = 0.f;
#pragma unroll
    for (int b = 0; b < NB; b++) acc += atanhf(fminf(nb[b], CLIPV)) / nb[b] * h[b];
    float tn = fmaxf(sqrtf(wsum(t * t)), MINN);
    acc += atanhf(fminf(tn, CLIPV)) / tn * t;
    acc *= (1.f / 9.f);
    float rn = fmaxf(sqrtf(wsum(acc * acc)), MINN);
    float on = tanhf(rn);
    float o = on / rn * acc;
    if (on > MAXNV) o *= MAXNV / on;
    out[(size_t)m * DIMD + lane] = o;
}

// ---------------- launch ----------------
extern "C" void kernel_launch(void* const* d_in, const int* in_sizes, int n_in,
                              void* d_out, int out_size) {
    const float* x  = (const float*)d_in[0];
    const int*   kr = (const int*)d_in[1];
    const int*   kc = (const int*)d_in[2];
    const float* kv = (const float*)d_in[3];
    const float* W1 = (const float*)d_in[4];
    const float* b1 = (const float*)d_in[5];
    const float* W2 = (const float*)d_in[6];
    const float* b2 = (const float*)d_in[7];
    float* out = (float*)d_out;

    const int smem1 = (32 * 260 + 32 * 68) * 4;  // 41984 B
    const int smem2 = (32 * 260 + 32 * 36) * 4;  // 37888 B
    cudaFuncSetAttribute(k_gemm<HIDD, FEATD, true>,
                         cudaFuncAttributeMaxDynamicSharedMemorySize, smem1);
    cudaFuncSetAttribute(k_gemm<DIMD, HIDD, false>,
                         cudaFuncAttributeMaxDynamicSharedMemorySize, smem2);

    int ggrid = (MN + 255) / 256;
    int agrid = (MN + 7) / 8;

    // one side stream + two events (leak-safe configuration proven in R12/R14)
    cudaStream_t sC;
    cudaStreamCreateWithFlags(&sC, cudaStreamNonBlocking);
    cudaEvent_t evFork, evCSR;
    cudaEventCreateWithFlags(&evFork, cudaEventDisableTiming);
    cudaEventCreateWithFlags(&evCSR, cudaEventDisableTiming);

    cudaEventRecord(evFork, 0);
    cudaStreamWaitEvent(sC, evFork, 0);

    // op1: bucket CSR build (side stream; counts pre-zeroed by prior call)
    k_place<<<dim3(EDG / 256, NB), 256, 0, sC>>>(kr, kc, kv);
    cudaEventRecord(evCSR, sC);

    // op2: features + biases (main)
    k_xhyp_bias<<<3126, 512>>>(x, b1, b2);
    // op3: layer-1 GEMM
    k_gemm<HIDD, FEATD, true><<<dim3(ggrid, NB), 256, smem1>>>(W1);
    // join CSR, then op4: agg1  <- profiled (4th kernel launch)
    cudaStreamWaitEvent(0, evCSR, 0);
    k_agg<HIDD><<<dim3(agrid, NB), 256>>>();
    // op5-7
    k_gemm<DIMD, HIDD, false><<<dim3(ggrid, NB), 256, smem2>>>(W2);
    k_agg<DIMD><<<dim3(agrid, NB), 256>>>();
    k_combine<<<agrid, 256>>>(out);
    // stream/events intentionally leaked (matches R12/R14 passing configuration;
    // destroying during capture is illegal)
}

// round 16
// speedup vs baseline: 1.4007x; 1.4007x over previous
#include <cuda_runtime.h>
#include <cuda_fp16.h>
#include <math.h>

// ---------------- problem constants ----------------
#define MN   50000
#define EDG  800000
#define NB   8
#define FEATD 128
#define HIDD  64
#define DIMD  32
#define CAP  64          // per-row edge bucket capacity (P(overflow) ~ e^-40)
#define MINN 1e-15f
#define CLIPV (1.0f - 1e-7f)
#define MAXNV (1.0f - 4e-3f)
#define FULLM 0xffffffffu

// ---------------- static scratch (no allocs allowed) ----------------
__device__ float g_xhyp[MN * FEATD];              // proj(expmap0(x))
__device__ float g_xn1[MN];                       // ||x_hyp|| per node
__device__ __align__(256) __half g_bufh[(size_t)NB * MN * HIDD]; // xt in fp16
__device__ float g_h[(size_t)NB * MN * HIDD];     // layer outputs (ball points)
__device__ float g_xn2[NB * MN];                  // ||h1|| per (branch,node)
__device__ int   g_count[NB * MN];                // zeroed by previous call's k_combine
__device__ int2  g_epack[(size_t)NB * MN * CAP];  // packed (col, val) per row bucket
__device__ float g_hb1[NB * HIDD];
__device__ float g_hb1n2[NB];
__device__ float g_hb2[NB * DIMD];
__device__ float g_hb2n2[NB];

__device__ __forceinline__ float wsum(float v) {
#pragma unroll
    for (int o = 16; o; o >>= 1) v += __shfl_xor_sync(FULLM, v, o);
    return v;
}
__device__ __forceinline__ float hsum8(float v) {
#pragma unroll
    for (int o = 4; o; o >>= 1) v += __shfl_xor_sync(FULLM, v, o);
    return v;
}

// packed fp32x2 helpers (Blackwell FFMA2 path)
__device__ __forceinline__ void ffma2(unsigned long long& d, unsigned long long a,
                                      unsigned long long b) {
    asm("fma.rn.f32x2 %0, %1, %2, %0;" : "+l"(d) : "l"(a), "l"(b));
}
__device__ __forceinline__ unsigned long long dup2(float x) {
    unsigned long long r;
    asm("mov.b64 %0, {%1, %1};" : "=l"(r) : "f"(x));
    return r;
}
__device__ __forceinline__ float2 unpk(unsigned long long v) {
    float2 r;
    asm("mov.b64 {%0, %1}, %2;" : "=f"(r.x), "=f"(r.y) : "l"(v));
    return r;
}

// ---------------- direct bucket CSR build (single pass) ----------------
__global__ void k_place(const int* __restrict__ rows, const int* __restrict__ cols,
                        const float* __restrict__ vals) {
    int b = blockIdx.y;
    int e = blockIdx.x * blockDim.x + threadIdx.x;
    size_t be = (size_t)b * EDG + e;
    int r = rows[be];
    int p = atomicAdd(&g_count[b * MN + r], 1);
    if (p < CAP)
        g_epack[((size_t)b * MN + r) * CAP + p] =
            make_int2(cols[be], __float_as_int(vals[be]));
}

// ---------------- x -> ball, fused with bias -> ball ----------------
__global__ void k_xhyp_bias(const float* __restrict__ x,
                            const float* __restrict__ b1,
                            const float* __restrict__ b2) {
    int lane = threadIdx.x & 31;
    if (blockIdx.x < 3125) {
        int m = blockIdx.x * 16 + (threadIdx.x >> 5);
        float u[4];
        float n2 = 0.f;
#pragma unroll
        for (int j = 0; j < 4; j++) {
            u[j] = x[(size_t)m * FEATD + lane + 32 * j];
            n2 += u[j] * u[j];
        }
        n2 = wsum(n2);
        float n = fmaxf(sqrtf(n2), MINN);
        float on = tanhf(n);
        float s = on / n;
        if (on > MAXNV) { s *= MAXNV / on; on = MAXNV; }
#pragma unroll
        for (int j = 0; j < 4; j++) g_xhyp[(size_t)m * FEATD + lane + 32 * j] = s * u[j];
        if (lane == 0) g_xn1[m] = fmaxf(on, MINN);
    } else {
        int wid = threadIdx.x >> 5;
        if (wid < NB) {
            int b = wid;
            float v0 = b1[b * HIDD + lane], v1 = b1[b * HIDD + lane + 32];
            float n = fmaxf(sqrtf(wsum(v0 * v0 + v1 * v1)), MINN);
            float on = tanhf(n);
            float s = on / n;
            if (on > MAXNV) { s *= MAXNV / on; on = MAXNV; }
            g_hb1[b * HIDD + lane] = s * v0;
            g_hb1[b * HIDD + lane + 32] = s * v1;
            if (lane == 0) g_hb1n2[b] = on * on;
        } else {
            int b = wid - 8;
            float v = b2[b * DIMD + lane];
            float n = fmaxf(sqrtf(wsum(v * v)), MINN);
            float on = tanhf(n);
            float s = on / n;
            if (on > MAXNV) { s *= MAXNV / on; on = MAXNV; }
            g_hb2[b * DIMD + lane] = s * v;
            if (lane == 0) g_hb2n2[b] = on * on;
        }
    }
}

// ---------------- SGEMM (f32x2 packed, KC=32) + fused mobius epilogue ----------------
// Tile: 256 rows x N cols, 256 threads, thread tile 8 x CN, K chunked by 32.
// 2 CTAs/SM (reg cap 128); smem traffic = 1 B/MAC. Epilogue -> fp16 g_bufh.
template <int N, int K, bool L1>
__global__ void __launch_bounds__(256, 2) k_gemm(const float* __restrict__ W) {
    constexpr int TM = 256, KC = 32, PX = TM + 4, PW = N + 4;
    constexpr int CN = (N == 64) ? 8 : 4;   // cols per thread (8 tx threads)
    constexpr int CP = CN / 2;              // packed col pairs
    extern __shared__ float smf[];
    float* Xs = smf;             // [KC][PX]
    float* Ws = smf + KC * PX;   // [KC][PW]
    int tid = threadIdx.x, b = blockIdx.y, m0 = blockIdx.x * TM;
    int tx = tid & 7, ty = tid >> 3;   // tx: 8 col-groups, ty: 32 row-groups
    const float* Xb = L1 ? g_xhyp : (g_h + (size_t)b * MN * K);

    unsigned long long acc[8][CP];
#pragma unroll
    for (int i = 0; i < 8; i++)
#pragma unroll
        for (int p = 0; p < CP; p++) acc[i][p] = 0ull;

    for (int kc0 = 0; kc0 < K; kc0 += KC) {
        __syncthreads();
        // fill X: TM rows x KC cols; t -> (m = t>>3, k4 = t&7)
#pragma unroll
        for (int it = 0; it < TM * (KC / 4) / 256; it++) {
            int t = tid + it * 256;
            int m = t >> 3, k4 = t & 7;
            int gm = m0 + m;
            float4 v = make_float4(0.f, 0.f, 0.f, 0.f);
            if (gm < MN) v = *(const float4*)(Xb + (size_t)gm * K + kc0 + k4 * 4);
            Xs[(k4 * 4 + 0) * PX + m] = v.x;
            Xs[(k4 * 4 + 1) * PX + m] = v.y;
            Xs[(k4 * 4 + 2) * PX + m] = v.z;
            Xs[(k4 * 4 + 3) * PX + m] = v.w;
        }
        // fill W: N rows x KC cols
        for (int t = tid; t < N * (KC / 4); t += 256) {
            int n = t >> 3, k4 = t & 7;
            float4 v = *(const float4*)(W + ((size_t)b * N + n) * K + kc0 + k4 * 4);
            Ws[(k4 * 4 + 0) * PW + n] = v.x;
            Ws[(k4 * 4 + 1) * PW + n] = v.y;
            Ws[(k4 * 4 + 2) * PW + n] = v.z;
            Ws[(k4 * 4 + 3) * PW + n] = v.w;
        }
        __syncthreads();
#pragma unroll 8
        for (int k = 0; k < KC; k++) {
            float4 a0 = *(const float4*)(Xs + k * PX + ty * 8);
            float4 a1 = *(const float4*)(Xs + k * PX + ty * 8 + 4);
            float av[8] = {a0.x, a0.y, a0.z, a0.w, a1.x, a1.y, a1.z, a1.w};
            unsigned long long bp[CP];
            const unsigned long long* bq =
                (const unsigned long long*)(Ws + k * PW + tx * CN);
#pragma unroll
            for (int p = 0; p < CP; p++) bp[p] = bq[p];
            unsigned long long ad[8];
#pragma unroll
            for (int i = 0; i < 8; i++) ad[i] = dup2(av[i]);
#pragma unroll
            for (int i = 0; i < 8; i++)
#pragma unroll
                for (int p = 0; p < CP; p++) ffma2(acc[i][p], ad[i], bp[p]);
        }
    }

    // ---- fused epilogue: row owned by 8 lanes (same ty) ----
    float hb[CN];
#pragma unroll
    for (int j = 0; j < CN; j++)
        hb[j] = L1 ? g_hb1[b * N + tx * CN + j] : g_hb2[b * N + tx * CN + j];
    float y2 = L1 ? g_hb1n2[b] : g_hb2n2[b];
#pragma unroll
    for (int i = 0; i < 8; i++) {
        int row = m0 + ty * 8 + i;
        float ac[CN];
#pragma unroll
        for (int p = 0; p < CP; p++) {
            float2 u = unpk(acc[i][p]);
            ac[2 * p] = u.x;
            ac[2 * p + 1] = u.y;
        }
        float s2 = 0.f;
#pragma unroll
        for (int j = 0; j < CN; j++) s2 += ac[j] * ac[j];
        float mxn = fmaxf(sqrtf(hsum8(s2)), MINN);
        float xn = 0.5f;
        if (row < MN) xn = L1 ? g_xn1[row] : g_xn2[(size_t)b * MN + row];
        float arg = mxn / xn * atanhf(fminf(xn, CLIPV));
        float th = tanhf(arg);
        float sc = th / mxn;
        float hn = th;
        if (hn > MAXNV) { sc *= MAXNV / hn; hn = MAXNV; }
        float h[CN];
#pragma unroll
        for (int j = 0; j < CN; j++) h[j] = sc * ac[j];
        float x2 = hn * hn;
        float xyp = 0.f;
#pragma unroll
        for (int j = 0; j < CN; j++) xyp += h[j] * hb[j];
        float xy = hsum8(xyp);
        float den = fmaxf(1.f + 2.f * xy + x2 * y2, MINN);
        float A = (1.f + 2.f * xy + y2) / den;
        float B = (1.f - x2) / den;
#pragma unroll
        for (int j = 0; j < CN; j++) h[j] = A * h[j] + B * hb[j];
        float rp = 0.f;
#pragma unroll
        for (int j = 0; j < CN; j++) rp += h[j] * h[j];
        float rn = fmaxf(sqrtf(hsum8(rp)), MINN);
        float pf = 1.f;
        if (rn > MAXNV) { pf = MAXNV / rn; rn = MAXNV; }
        float t = atanhf(fminf(rn, CLIPV)) / rn * pf;
        if (row < MN) {
            __half2 hv[CP];
#pragma unroll
            for (int p = 0; p < CP; p++)
                hv[p] = __float22half2_rn(make_float2(t * h[2 * p], t * h[2 * p + 1]));
            __half* o = g_bufh + ((size_t)b * MN + row) * N + tx * CN;
            if (CP == 4) *(uint4*)o = *(uint4*)hv;
            else         *(uint2*)o = *(uint2*)hv;
        }
    }
}

// ---------------- bucket gather agg: LPR lanes per row, RPW rows per warp ----------------
// Per lane: 4 dims (one uint2 = 4 halves). Edge broadcast via width-LPR shuffles.
// All groups in a warp loop to the warp-max count with zero-weight padding.
template <int D>
__global__ void k_agg() {
    constexpr int LPR = D / 4;        // 16 (D=64) or 8 (D=32) lanes per row
    constexpr int RPW = 32 / LPR;     // 2 or 4 rows per warp
    constexpr int RPB = 8 * RPW;      // rows per 256-thread block
    int b = blockIdx.y;
    int warp = threadIdx.x >> 5, lane = threadIdx.x & 31;
    int sub = lane / LPR, sl = lane % LPR;
    int m = blockIdx.x * RPB + warp * RPW + sub;
    bool valid = (m < MN);
    int mm = valid ? m : 0;
    int cnt = valid ? min(g_count[b * MN + mm], CAP) : 0;
    // warp-wide max trip count (mix across groups only)
    int cmax = cnt;
#pragma unroll
    for (int o = LPR; o < 32; o <<= 1) cmax = max(cmax, __shfl_xor_sync(FULLM, cmax, o));

    const int2* __restrict__ ep = g_epack + ((size_t)b * MN + mm) * CAP;
    const __half* __restrict__ xt = g_bufh + (size_t)b * MN * D;
    float acc[4] = {0.f, 0.f, 0.f, 0.f};
    float acc2[4] = {0.f, 0.f, 0.f, 0.f};

    for (int base = 0; base < cmax; base += LPR) {
        int c = 0; float v = 0.f;
        if (base + sl < cnt) {
            int2 pk = ep[base + sl];
            c = pk.x;
            v = __int_as_float(pk.y);
        }
        int lim = min(LPR, cmax - base);
        int j = 0;
        for (; j + 8 <= lim; j += 8) {
            int e[8]; float w[8];
#pragma unroll
            for (int u = 0; u < 8; u++) {
                e[u] = __shfl_sync(FULLM, c, j + u, LPR);
                w[u] = __shfl_sync(FULLM, v, j + u, LPR);
            }
            uint2 rv[8];
#pragma unroll
            for (int u = 0; u < 8; u++)
                rv[u] = __ldg((const uint2*)(xt + (size_t)e[u] * D) + sl);
#pragma unroll
            for (int u = 0; u < 8; u += 2) {
                float2 f0 = __half22float2(*(__half2*)&rv[u].x);
                float2 f1 = __half22float2(*(__half2*)&rv[u].y);
                acc[0] += w[u] * f0.x; acc[1] += w[u] * f0.y;
                acc[2] += w[u] * f1.x; acc[3] += w[u] * f1.y;
                float2 g0 = __half22float2(*(__half2*)&rv[u + 1].x);
                float2 g1 = __half22float2(*(__half2*)&rv[u + 1].y);
                acc2[0] += w[u + 1] * g0.x; acc2[1] += w[u + 1] * g0.y;
                acc2[2] += w[u + 1] * g1.x; acc2[3] += w[u + 1] * g1.y;
            }
        }
        for (; j < lim; j++) {
            int ej = __shfl_sync(FULLM, c, j, LPR);
            float wj = __shfl_sync(FULLM, v, j, LPR);
            uint2 rv = __ldg((const uint2*)(xt + (size_t)ej * D) + sl);
            float2 f0 = __half22float2(*(__half2*)&rv.x);
            float2 f1 = __half22float2(*(__half2*)&rv.y);
            acc[0] += wj * f0.x; acc[1] += wj * f0.y;
            acc[2] += wj * f1.x; acc[3] += wj * f1.y;
        }
    }
#pragma unroll
    for (int d = 0; d < 4; d++) acc[d] += acc2[d];

    // group-wide (width LPR) reduction helpers inline
    float n2 = 0.f;
#pragma unroll
    for (int d = 0; d < 4; d++) n2 += acc[d] * acc[d];
#pragma unroll
    for (int o = LPR / 2; o; o >>= 1) n2 += __shfl_xor_sync(FULLM, n2, o);
    // h = proj(expmap0(agg))
    float n = fmaxf(sqrtf(n2), MINN);
    float th = tanhf(n);
    float s = th / n;
    float h4[4];
#pragma unroll
    for (int d = 0; d < 4; d++) h4[d] = s * acc[d];
    float hn = th;
    if (hn > MAXNV) {
        float f = MAXNV / hn;
#pragma unroll
        for (int d = 0; d < 4; d++) h4[d] *= f;
        hn = MAXNV;
    }
    // u = relu(logmap0(h))
    float lt = atanhf(fminf(hn, CLIPV)) / fmaxf(hn, MINN);
    float u4[4];
#pragma unroll
    for (int d = 0; d < 4; d++) u4[d] = fmaxf(lt * h4[d], 0.f);
    // o = proj(expmap0(u))
    float un2 = 0.f;
#pragma unroll
    for (int d = 0; d < 4; d++) un2 += u4[d] * u4[d];
#pragma unroll
    for (int o = LPR / 2; o; o >>= 1) un2 += __shfl_xor_sync(FULLM, un2, o);
    float un = fmaxf(sqrtf(un2), MINN);
    float ot = tanhf(un);
    float os = ot / un;
    float o4[4];
#pragma unroll
    for (int d = 0; d < 4; d++) o4[d] = os * u4[d];
    float on = ot;
    if (on > MAXNV) {
        float f = MAXNV / on;
#pragma unroll
        for (int d = 0; d < 4; d++) o4[d] *= f;
        on = MAXNV;
    }
    if (valid) {
        *(float4*)(g_h + ((size_t)b * MN + m) * D + 4 * sl) =
            make_float4(o4[0], o4[1], o4[2], o4[3]);
        if (D == 64 && sl == 0) g_xn2[b * MN + m] = fmaxf(on, MINN);
    }
}

// ---------------- final fold + attention-agg row0 (+ reset g_count) ----------------
__global__ void k_combine(float* __restrict__ out) {
    // reset edge counters for the next invocation (deterministic per-call state)
    int gid = blockIdx.x * blockDim.x + threadIdx.x;
    if (gid < NB * MN) g_count[gid] = 0;

    int m = blockIdx.x * 8 + (threadIdx.x >> 5);
    if (m >= MN) return;
    int lane = threadIdx.x & 31;
    float h[NB], nb[NB], sw[NB], wn2[NB];
#pragma unroll
    for (int b = 0; b < NB; b++) {
        h[b] = g_h[((size_t)b * MN + m) * DIMD + lane];
        nb[b] = fmaxf(sqrtf(wsum(h[b] * h[b])), MINN);
        float a = tanhf(0.125f * atanhf(fminf(nb[b], CLIPV)));
        sw[b] = a / nb[b];
        wn2[b] = a * a;
    }
    float t = sw[0] * h[0];
#pragma unroll
    for (int b = 1; b < NB; b++) {
        float x2 = wsum(t * t);
        float wv = sw[b] * h[b];
        float y2 = wn2[b];
        float xy = wsum(t * wv);
        float den = fmaxf(1.f + 2.f * xy + x2 * y2, MINN);
        t = ((1.f + 2.f * xy + y2) * t + (1.f - x2) * wv) / den;
    }
    float acc = 0.f;
#pragma unroll
    for (int b = 0; b < NB; b++) acc += atanhf(fminf(nb[b], CLIPV)) / nb[b] * h[b];
    float tn = fmaxf(sqrtf(wsum(t * t)), MINN);
    acc += atanhf(fminf(tn, CLIPV)) / tn * t;
    acc *= (1.f / 9.f);
    float rn = fmaxf(sqrtf(wsum(acc * acc)), MINN);
    float on = tanhf(rn);
    float o = on / rn * acc;
    if (on > MAXNV) o *= MAXNV / on;
    out[(size_t)m * DIMD + lane] = o;
}

// ---------------- launch ----------------
extern "C" void kernel_launch(void* const* d_in, const int* in_sizes, int n_in,
                              void* d_out, int out_size) {
    const float* x  = (const float*)d_in[0];
    const int*   kr = (const int*)d_in[1];
    const int*   kc = (const int*)d_in[2];
    const float* kv = (const float*)d_in[3];
    const float* W1 = (const float*)d_in[4];
    const float* b1 = (const float*)d_in[5];
    const float* W2 = (const float*)d_in[6];
    const float* b2 = (const float*)d_in[7];
    float* out = (float*)d_out;

    const int smem1 = (32 * 260 + 32 * 68) * 4;  // 41984 B
    const int smem2 = (32 * 260 + 32 * 36) * 4;  // 37888 B
    cudaFuncSetAttribute(k_gemm<HIDD, FEATD, true>,
                         cudaFuncAttributeMaxDynamicSharedMemorySize, smem1);
    cudaFuncSetAttribute(k_gemm<DIMD, HIDD, false>,
                         cudaFuncAttributeMaxDynamicSharedMemorySize, smem2);

    int ggrid = (MN + 255) / 256;
    int agrid1 = (MN + 15) / 16;   // k_agg<64>: 16 rows/block
    int agrid2 = (MN + 31) / 32;   // k_agg<32>: 32 rows/block

    // one side stream + two events (leak-safe configuration proven in R12/R14)
    cudaStream_t sC;
    cudaStreamCreateWithFlags(&sC, cudaStreamNonBlocking);
    cudaEvent_t evFork, evCSR;
    cudaEventCreateWithFlags(&evFork, cudaEventDisableTiming);
    cudaEventCreateWithFlags(&evCSR, cudaEventDisableTiming);

    cudaEventRecord(evFork, 0);
    cudaStreamWaitEvent(sC, evFork, 0);

    // op1: bucket CSR build (side stream; counts pre-zeroed by prior call)
    k_place<<<dim3(EDG / 256, NB), 256, 0, sC>>>(kr, kc, kv);
    cudaEventRecord(evCSR, sC);

    // op2: features + biases (main)
    k_xhyp_bias<<<3126, 512>>>(x, b1, b2);
    // op3: layer-1 GEMM
    k_gemm<HIDD, FEATD, true><<<dim3(ggrid, NB), 256, smem1>>>(W1);
    // join CSR, then op4: agg1  <- profiled (4th kernel launch)
    cudaStreamWaitEvent(0, evCSR, 0);
    k_agg<HIDD><<<dim3(agrid1, NB), 256>>>();
    // op5-7
    k_gemm<DIMD, HIDD, false><<<dim3(ggrid, NB), 256, smem2>>>(W2);
    k_agg<DIMD><<<dim3(agrid2, NB), 256>>>();
    k_combine<<<(MN + 7) / 8, 256>>>(out);
    // stream/events intentionally leaked (matches R12/R14 passing configuration;
    // destroying during capture is illegal)
}

// round 17
// speedup vs baseline: 1.7753x; 1.2674x over previous
#include <cuda_runtime.h>
#include <cuda_fp16.h>
#include <math.h>

// ---------------- problem constants ----------------
#define MN   50000
#define EDG  800000
#define NB   8
#define FEATD 128
#define HIDD  64
#define DIMD  32
#define CAP  64          // per-row edge bucket capacity (P(overflow) ~ e^-40)
#define MINN 1e-15f
#define CLIPV (1.0f - 1e-7f)
#define MAXNV (1.0f - 4e-3f)
#define FULLM 0xffffffffu

// ---------------- static scratch (no allocs allowed) ----------------
__device__ float g_xhyp[MN * FEATD];              // proj(expmap0(x))
__device__ float g_xn1[MN];                       // ||x_hyp|| per node
__device__ __align__(256) __half g_bufh[(size_t)NB * MN * HIDD]; // xt in fp16
__device__ float g_h[(size_t)NB * MN * HIDD];     // layer outputs (ball points)
__device__ float g_xn2[NB * MN];                  // ||h1|| per (branch,node)
__device__ int   g_count[NB * MN];                // zeroed by previous call's k_combine
__device__ int2  g_epack[(size_t)NB * MN * CAP];  // packed (col, val) per row bucket
__device__ float g_hb1[NB * HIDD];
__device__ float g_hb1n2[NB];
__device__ float g_hb2[NB * DIMD];
__device__ float g_hb2n2[NB];

__device__ __forceinline__ float wsum(float v) {
#pragma unroll
    for (int o = 16; o; o >>= 1) v += __shfl_xor_sync(FULLM, v, o);
    return v;
}
__device__ __forceinline__ float hsum4(float v) {
    v += __shfl_xor_sync(FULLM, v, 1);
    v += __shfl_xor_sync(FULLM, v, 2);
    return v;
}

// m16n8k16 f16 MMA, fp32 accum (HMMA)
__device__ __forceinline__ void mma16816(float* c, const unsigned* a, const unsigned* b) {
    asm volatile(
        "mma.sync.aligned.m16n8k16.row.col.f32.f16.f16.f32 "
        "{%0,%1,%2,%3}, {%4,%5,%6,%7}, {%8,%9}, {%0,%1,%2,%3};"
        : "+f"(c[0]), "+f"(c[1]), "+f"(c[2]), "+f"(c[3])
        : "r"(a[0]), "r"(a[1]), "r"(a[2]), "r"(a[3]), "r"(b[0]), "r"(b[1]));
}

// ---------------- direct bucket CSR build (single pass) ----------------
__global__ void k_place(const int* __restrict__ rows, const int* __restrict__ cols,
                        const float* __restrict__ vals) {
    int b = blockIdx.y;
    int e = blockIdx.x * blockDim.x + threadIdx.x;
    size_t be = (size_t)b * EDG + e;
    int r = rows[be];
    int p = atomicAdd(&g_count[b * MN + r], 1);
    if (p < CAP)
        g_epack[((size_t)b * MN + r) * CAP + p] =
            make_int2(cols[be], __float_as_int(vals[be]));
}

// ---------------- x -> ball, fused with bias -> ball ----------------
__global__ void k_xhyp_bias(const float* __restrict__ x,
                            const float* __restrict__ b1,
                            const float* __restrict__ b2) {
    int lane = threadIdx.x & 31;
    if (blockIdx.x < 3125) {
        int m = blockIdx.x * 16 + (threadIdx.x >> 5);
        float u[4];
        float n2 = 0.f;
#pragma unroll
        for (int j = 0; j < 4; j++) {
            u[j] = x[(size_t)m * FEATD + lane + 32 * j];
            n2 += u[j] * u[j];
        }
        n2 = wsum(n2);
        float n = fmaxf(sqrtf(n2), MINN);
        float on = tanhf(n);
        float s = on / n;
        if (on > MAXNV) { s *= MAXNV / on; on = MAXNV; }
#pragma unroll
        for (int j = 0; j < 4; j++) g_xhyp[(size_t)m * FEATD + lane + 32 * j] = s * u[j];
        if (lane == 0) g_xn1[m] = fmaxf(on, MINN);
    } else {
        int wid = threadIdx.x >> 5;
        if (wid < NB) {
            int b = wid;
            float v0 = b1[b * HIDD + lane], v1 = b1[b * HIDD + lane + 32];
            float n = fmaxf(sqrtf(wsum(v0 * v0 + v1 * v1)), MINN);
            float on = tanhf(n);
            float s = on / n;
            if (on > MAXNV) { s *= MAXNV / on; on = MAXNV; }
            g_hb1[b * HIDD + lane] = s * v0;
            g_hb1[b * HIDD + lane + 32] = s * v1;
            if (lane == 0) g_hb1n2[b] = on * on;
        } else {
            int b = wid - 8;
            float v = b2[b * DIMD + lane];
            float n = fmaxf(sqrtf(wsum(v * v)), MINN);
            float on = tanhf(n);
            float s = on / n;
            if (on > MAXNV) { s *= MAXNV / on; on = MAXNV; }
            g_hb2[b * DIMD + lane] = s * v;
            if (lane == 0) g_hb2n2[b] = on * on;
        }
    }
}

// ---------------- tensor-core GEMM (m16n8k16 HMMA) + fused mobius epilogue ----------------
// Tile: 256 rows x N cols, 256 threads = 8 warps, warp tile 32 x N.
// A (fp32 global) converted to fp16 in smem; W converted likewise.
// mx[b][m][n] = sum_k X[m][k] * W[b][n][k]; epilogue writes xt -> fp16 g_bufh.
template <int N, int K, bool L1>
__global__ void __launch_bounds__(256, 2) k_gemm(const float* __restrict__ W) {
    constexpr int TM = 256, PA = K + 8, NA = N / 8;
    extern __shared__ __half smh[];
    __half* As = smh;              // [TM][PA]
    __half* Bs = smh + TM * PA;    // [N][PA]
    int tid = threadIdx.x, b = blockIdx.y, m0 = blockIdx.x * TM;
    int warp = tid >> 5, lane = tid & 31;
    int g = lane >> 2, tig = lane & 3;
    const float* Xb = L1 ? g_xhyp : (g_h + (size_t)b * MN * K);

    // fill A (convert fp32 -> fp16)
#pragma unroll
    for (int it = 0; it < TM * (K / 4) / 256; it++) {
        int t = tid + it * 256;
        int m = t / (K / 4), k4 = t % (K / 4);
        int gm = m0 + m;
        float4 v = make_float4(0.f, 0.f, 0.f, 0.f);
        if (gm < MN) v = *(const float4*)(Xb + (size_t)gm * K + k4 * 4);
        __half2 h0 = __float22half2_rn(make_float2(v.x, v.y));
        __half2 h1 = __float22half2_rn(make_float2(v.z, v.w));
        *(uint2*)&As[m * PA + k4 * 4] =
            make_uint2(*(unsigned*)&h0, *(unsigned*)&h1);
    }
    // fill B
    for (int t = tid; t < N * (K / 4); t += 256) {
        int n = t / (K / 4), k4 = t % (K / 4);
        float4 v = *(const float4*)(W + ((size_t)b * N + n) * K + k4 * 4);
        __half2 h0 = __float22half2_rn(make_float2(v.x, v.y));
        __half2 h1 = __float22half2_rn(make_float2(v.z, v.w));
        *(uint2*)&Bs[n * PA + k4 * 4] =
            make_uint2(*(unsigned*)&h0, *(unsigned*)&h1);
    }
    __syncthreads();

    float acc[2][NA][4];
#pragma unroll
    for (int ma = 0; ma < 2; ma++)
#pragma unroll
        for (int na = 0; na < NA; na++)
#pragma unroll
            for (int q = 0; q < 4; q++) acc[ma][na][q] = 0.f;

#pragma unroll
    for (int k0 = 0; k0 < K; k0 += 16) {
        unsigned a[2][4];
#pragma unroll
        for (int ma = 0; ma < 2; ma++) {
            int r0 = warp * 32 + ma * 16 + g;
            a[ma][0] = *(unsigned*)&As[r0 * PA + k0 + tig * 2];
            a[ma][1] = *(unsigned*)&As[(r0 + 8) * PA + k0 + tig * 2];
            a[ma][2] = *(unsigned*)&As[r0 * PA + k0 + tig * 2 + 8];
            a[ma][3] = *(unsigned*)&As[(r0 + 8) * PA + k0 + tig * 2 + 8];
        }
        unsigned bf[NA][2];
#pragma unroll
        for (int na = 0; na < NA; na++) {
            int n = na * 8 + g;
            bf[na][0] = *(unsigned*)&Bs[n * PA + k0 + tig * 2];
            bf[na][1] = *(unsigned*)&Bs[n * PA + k0 + tig * 2 + 8];
        }
#pragma unroll
        for (int ma = 0; ma < 2; ma++)
#pragma unroll
            for (int na = 0; na < NA; na++)
                mma16816(acc[ma][na], a[ma], bf[na]);
    }

    // ---- fused mobius epilogue on c-fragments ----
    // lane holds rows {g, g+8} per m-atom, cols {na*8 + tig*2, +1}.
    float hb[NA][2];
#pragma unroll
    for (int na = 0; na < NA; na++) {
        const float* hbs = L1 ? g_hb1 : g_hb2;
        hb[na][0] = hbs[b * N + na * 8 + tig * 2];
        hb[na][1] = hbs[b * N + na * 8 + tig * 2 + 1];
    }
    float y2 = L1 ? g_hb1n2[b] : g_hb2n2[b];
#pragma unroll
    for (int ma = 0; ma < 2; ma++) {
#pragma unroll
        for (int hf = 0; hf < 2; hf++) {
            int row = m0 + warp * 32 + ma * 16 + g + hf * 8;
            float v0[NA], v1[NA];
#pragma unroll
            for (int na = 0; na < NA; na++) {
                v0[na] = acc[ma][na][hf * 2];
                v1[na] = acc[ma][na][hf * 2 + 1];
            }
            float s2 = 0.f;
#pragma unroll
            for (int na = 0; na < NA; na++) s2 += v0[na] * v0[na] + v1[na] * v1[na];
            float mxn = fmaxf(sqrtf(hsum4(s2)), MINN);
            float xn = 0.5f;
            if (row < MN) xn = L1 ? g_xn1[row] : g_xn2[(size_t)b * MN + row];
            float arg = mxn / xn * atanhf(fminf(xn, CLIPV));
            float th = tanhf(arg);
            float sc = th / mxn;
            float hn = th;
            if (hn > MAXNV) { sc *= MAXNV / hn; hn = MAXNV; }
#pragma unroll
            for (int na = 0; na < NA; na++) { v0[na] *= sc; v1[na] *= sc; }
            float x2 = hn * hn;
            float xyp = 0.f;
#pragma unroll
            for (int na = 0; na < NA; na++)
                xyp += v0[na] * hb[na][0] + v1[na] * hb[na][1];
            float xy = hsum4(xyp);
            float den = fmaxf(1.f + 2.f * xy + x2 * y2, MINN);
            float A_ = (1.f + 2.f * xy + y2) / den;
            float B_ = (1.f - x2) / den;
#pragma unroll
            for (int na = 0; na < NA; na++) {
                v0[na] = A_ * v0[na] + B_ * hb[na][0];
                v1[na] = A_ * v1[na] + B_ * hb[na][1];
            }
            float rp = 0.f;
#pragma unroll
            for (int na = 0; na < NA; na++) rp += v0[na] * v0[na] + v1[na] * v1[na];
            float rn = fmaxf(sqrtf(hsum4(rp)), MINN);
            float pf = 1.f;
            if (rn > MAXNV) { pf = MAXNV / rn; rn = MAXNV; }
            float t = atanhf(fminf(rn, CLIPV)) / rn * pf;
            if (row < MN) {
                __half* o = g_bufh + ((size_t)b * MN + row) * N;
#pragma unroll
                for (int na = 0; na < NA; na++) {
                    __half2 hv = __float22half2_rn(
                        make_float2(t * v0[na], t * v1[na]));
                    *(unsigned*)&o[na * 8 + tig * 2] = *(unsigned*)&hv;
                }
            }
        }
    }
}

// ---------------- bucket gather agg: LPR lanes per row, RPW rows per warp ----------------
template <int D>
__global__ void k_agg() {
    constexpr int LPR = D / 4;        // 16 (D=64) or 8 (D=32) lanes per row
    constexpr int RPW = 32 / LPR;     // 2 or 4 rows per warp
    constexpr int RPB = 8 * RPW;      // rows per 256-thread block
    int b = blockIdx.y;
    int warp = threadIdx.x >> 5, lane = threadIdx.x & 31;
    int sub = lane / LPR, sl = lane % LPR;
    int m = blockIdx.x * RPB + warp * RPW + sub;
    bool valid = (m < MN);
    int mm = valid ? m : 0;
    int cnt = valid ? min(g_count[b * MN + mm], CAP) : 0;
    int cmax = cnt;
#pragma unroll
    for (int o = LPR; o < 32; o <<= 1) cmax = max(cmax, __shfl_xor_sync(FULLM, cmax, o));

    const int2* __restrict__ ep = g_epack + ((size_t)b * MN + mm) * CAP;
    const __half* __restrict__ xt = g_bufh + (size_t)b * MN * D;
    float acc[4] = {0.f, 0.f, 0.f, 0.f};
    float acc2[4] = {0.f, 0.f, 0.f, 0.f};

    for (int base = 0; base < cmax; base += LPR) {
        int c = 0; float v = 0.f;
        if (base + sl < cnt) {
            int2 pk = ep[base + sl];
            c = pk.x;
            v = __int_as_float(pk.y);
        }
        int lim = min(LPR, cmax - base);
        int j = 0;
        for (; j + 8 <= lim; j += 8) {
            int e[8]; float w[8];
#pragma unroll
            for (int u = 0; u < 8; u++) {
                e[u] = __shfl_sync(FULLM, c, j + u, LPR);
                w[u] = __shfl_sync(FULLM, v, j + u, LPR);
            }
            uint2 rv[8];
#pragma unroll
            for (int u = 0; u < 8; u++)
                rv[u] = __ldg((const uint2*)(xt + (size_t)e[u] * D) + sl);
#pragma unroll
            for (int u = 0; u < 8; u += 2) {
                float2 f0 = __half22float2(*(__half2*)&rv[u].x);
                float2 f1 = __half22float2(*(__half2*)&rv[u].y);
                acc[0] += w[u] * f0.x; acc[1] += w[u] * f0.y;
                acc[2] += w[u] * f1.x; acc[3] += w[u] * f1.y;
                float2 g0 = __half22float2(*(__half2*)&rv[u + 1].x);
                float2 g1 = __half22float2(*(__half2*)&rv[u + 1].y);
                acc2[0] += w[u + 1] * g0.x; acc2[1] += w[u + 1] * g0.y;
                acc2[2] += w[u + 1] * g1.x; acc2[3] += w[u + 1] * g1.y;
            }
        }
        for (; j < lim; j++) {
            int ej = __shfl_sync(FULLM, c, j, LPR);
            float wj = __shfl_sync(FULLM, v, j, LPR);
            uint2 rv = __ldg((const uint2*)(xt + (size_t)ej * D) + sl);
            float2 f0 = __half22float2(*(__half2*)&rv.x);
            float2 f1 = __half22float2(*(__half2*)&rv.y);
            acc[0] += wj * f0.x; acc[1] += wj * f0.y;
            acc[2] += wj * f1.x; acc[3] += wj * f1.y;
        }
    }
#pragma unroll
    for (int d = 0; d < 4; d++) acc[d] += acc2[d];

    float n2 = 0.f;
#pragma unroll
    for (int d = 0; d < 4; d++) n2 += acc[d] * acc[d];
#pragma unroll
    for (int o = LPR / 2; o; o >>= 1) n2 += __shfl_xor_sync(FULLM, n2, o);
    float n = fmaxf(sqrtf(n2), MINN);
    float th = tanhf(n);
    float s = th / n;
    float h4[4];
#pragma unroll
    for (int d = 0; d < 4; d++) h4[d] = s * acc[d];
    float hn = th;
    if (hn > MAXNV) {
        float f = MAXNV / hn;
#pragma unroll
        for (int d = 0; d < 4; d++) h4[d] *= f;
        hn = MAXNV;
    }
    float lt = atanhf(fminf(hn, CLIPV)) / fmaxf(hn, MINN);
    float u4[4];
#pragma unroll
    for (int d = 0; d < 4; d++) u4[d] = fmaxf(lt * h4[d], 0.f);
    float un2 = 0.f;
#pragma unroll
    for (int d = 0; d < 4; d++) un2 += u4[d] * u4[d];
#pragma unroll
    for (int o = LPR / 2; o; o >>= 1) un2 += __shfl_xor_sync(FULLM, un2, o);
    float un = fmaxf(sqrtf(un2), MINN);
    float ot = tanhf(un);
    float os = ot / un;
    float o4[4];
#pragma unroll
    for (int d = 0; d < 4; d++) o4[d] = os * u4[d];
    float on = ot;
    if (on > MAXNV) {
        float f = MAXNV / on;
#pragma unroll
        for (int d = 0; d < 4; d++) o4[d] *= f;
        on = MAXNV;
    }
    if (valid) {
        *(float4*)(g_h + ((size_t)b * MN + m) * D + 4 * sl) =
            make_float4(o4[0], o4[1], o4[2], o4[3]);
        if (D == 64 && sl == 0) g_xn2[b * MN + m] = fmaxf(on, MINN);
    }
}

// ---------------- final fold + attention-agg row0 (+ reset g_count) ----------------
__global__ void k_combine(float* __restrict__ out) {
    int gid = blockIdx.x * blockDim.x + threadIdx.x;
    if (gid < NB * MN) g_count[gid] = 0;

    int m = blockIdx.x * 8 + (threadIdx.x >> 5);
    if (m >= MN) return;
    int lane = threadIdx.x & 31;
    float h[NB], nb[NB], sw[NB], wn2[NB];
#pragma unroll
    for (int b = 0; b < NB; b++) {
        h[b] = g_h[((size_t)b * MN + m) * DIMD + lane];
        nb[b] = fmaxf(sqrtf(wsum(h[b] * h[b])), MINN);
        float a = tanhf(0.125f * atanhf(fminf(nb[b], CLIPV)));
        sw[b] = a / nb[b];
        wn2[b] = a * a;
    }
    float t = sw[0] * h[0];
#pragma unroll
    for (int b = 1; b < NB; b++) {
        float x2 = wsum(t * t);
        float wv = sw[b] * h[b];
        float y2 = wn2[b];
        float xy = wsum(t * wv);
        float den = fmaxf(1.f + 2.f * xy + x2 * y2, MINN);
        t = ((1.f + 2.f * xy + y2) * t + (1.f - x2) * wv) / den;
    }
    float acc = 0.f;
#pragma unroll
    for (int b = 0; b < NB; b++) acc += atanhf(fminf(nb[b], CLIPV)) / nb[b] * h[b];
    float tn = fmaxf(sqrtf(wsum(t * t)), MINN);
    acc += atanhf(fminf(tn, CLIPV)) / tn * t;
    acc *= (1.f / 9.f);
    float rn = fmaxf(sqrtf(wsum(acc * acc)), MINN);
    float on = tanhf(rn);
    float o = on / rn * acc;
    if (on > MAXNV) o *= MAXNV / on;
    out[(size_t)m * DIMD + lane] = o;
}

// ---------------- launch ----------------
extern "C" void kernel_launch(void* const* d_in, const int* in_sizes, int n_in,
                              void* d_out, int out_size) {
    const float* x  = (const float*)d_in[0];
    const int*   kr = (const int*)d_in[1];
    const int*   kc = (const int*)d_in[2];
    const float* kv = (const float*)d_in[3];
    const float* W1 = (const float*)d_in[4];
    const float* b1 = (const float*)d_in[5];
    const float* W2 = (const float*)d_in[6];
    const float* b2 = (const float*)d_in[7];
    float* out = (float*)d_out;

    // smem: (TM + N) * (K + 8) halves
    const int smem1 = (256 + 64) * (128 + 8) * 2;  // 87040 B
    const int smem2 = (256 + 32) * (64 + 8) * 2;   // 41472 B
    cudaFuncSetAttribute(k_gemm<HIDD, FEATD, true>,
                         cudaFuncAttributeMaxDynamicSharedMemorySize, smem1);
    cudaFuncSetAttribute(k_gemm<DIMD, HIDD, false>,
                         cudaFuncAttributeMaxDynamicSharedMemorySize, smem2);

    int ggrid = (MN + 255) / 256;
    int agrid1 = (MN + 15) / 16;   // k_agg<64>: 16 rows/block
    int agrid2 = (MN + 31) / 32;   // k_agg<32>: 32 rows/block

    // one side stream + two events (leak-safe configuration proven in R12/R14/R16)
    cudaStream_t sC;
    cudaStreamCreateWithFlags(&sC, cudaStreamNonBlocking);
    cudaEvent_t evFork, evCSR;
    cudaEventCreateWithFlags(&evFork, cudaEventDisableTiming);
    cudaEventCreateWithFlags(&evCSR, cudaEventDisableTiming);

    cudaEventRecord(evFork, 0);
    cudaStreamWaitEvent(sC, evFork, 0);

    // op1: bucket CSR build (side stream; counts pre-zeroed by prior call)
    k_place<<<dim3(EDG / 256, NB), 256, 0, sC>>>(kr, kc, kv);
    cudaEventRecord(evCSR, sC);

    // op2: features + biases (main)
    k_xhyp_bias<<<3126, 512>>>(x, b1, b2);
    // op3: layer-1 GEMM (tensor cores)
    k_gemm<HIDD, FEATD, true><<<dim3(ggrid, NB), 256, smem1>>>(W1);
    // join CSR, then op4: agg1  <- profiled (4th kernel launch)
    cudaStreamWaitEvent(0, evCSR, 0);
    k_agg<HIDD><<<dim3(agrid1, NB), 256>>>();
    // op5-7
    k_gemm<DIMD, HIDD, false><<<dim3(ggrid, NB), 256, smem2>>>(W2);
    k_agg<DIMD><<<dim3(agrid2, NB), 256>>>();
    k_combine<<<(MN + 7) / 8, 256>>>(out);
    // stream/events intentionally leaked (proven leak-safe; destroying during
    // capture is illegal)
}